// round 16
// baseline (speedup 1.0000x reference)
#include <cuda_runtime.h>

#define BATCH 2048
#define CELL 512
#define KDIM 30
#define LPAD 1024
#define VDIM 80

// ---------------------------------------------------------------------------
// Kernel A: fused params + sparse phi.  Stage 1 is the r14 measured-best GEMM
// (8 batches/block, 8 warps, launch_bounds(256,2), 8 batch accumulators,
// 9-shfl merged fold — 25.0us, regs=128, no spills).  Stage 2 computes sparse
// phi in-block (Gaussian k only where beta*(kappa-l)^2 < 92; beyond that expf
// underflows to 0, matching the fp32 reference), eliminating the separate phi
// launch and the g_params global round-trip.
// ---------------------------------------------------------------------------
__global__ __launch_bounds__(256, 2) void params_phi_kernel(
    const float* __restrict__ x,          // [B, CELL]
    const float* __restrict__ kappa_old,  // [B, K]
    const float* __restrict__ text_lens,  // [B, 1]
    const float* __restrict__ W,          // [3K, CELL]
    const float* __restrict__ bias,       // [3K]
    float* __restrict__ out_kappa,        // [B, K]
    float* __restrict__ out_phi)          // [B, L+1]
{
    __shared__ float4 xs[8][CELL / 4 + 1];   // 16.5 KB, rows bank-shifted
    __shared__ float s_par[8][3 * KDIM];     // alpha | beta | kappa per batch
    __shared__ float s_phi[8][LPAD + 1];     // 32.8 KB
    __shared__ float s_scale[8];
    __shared__ float s_bias[3 * KDIM];

    const int tid = threadIdx.x;
    const int wid = tid >> 5;                // 8 warps
    const int lane = tid & 31;
    const int b0 = blockIdx.x * 8;

    const float4* xg = (const float4*)(x + (size_t)b0 * CELL);
    for (int i = tid; i < 8 * CELL / 4; i += 256) {
        int r = i >> 7;
        int j = i & 127;
        xs[r][j] = xg[r * 128 + j];
    }
    if (tid < 3 * KDIM) s_bias[tid] = bias[tid];
    if (tid < 8) s_scale[tid] = (float)LPAD / text_lens[b0 + tid];
    for (int i = tid; i < 8 * (LPAD + 1); i += 256) {
        int r = i / (LPAD + 1);
        int l = i - r * (LPAD + 1);
        s_phi[r][l] = 0.0f;
    }
    __syncthreads();

    // ---- stage 1: 90 outputs round-robin over 8 warps, 8 batch accs ----
    for (int o = wid; o < 3 * KDIM; o += 8) {
        const float4* wrow = (const float4*)(W + (size_t)o * CELL);
        float a[8];
        #pragma unroll
        for (int r = 0; r < 8; r++) a[r] = 0.0f;

        #pragma unroll
        for (int j4 = 0; j4 < 4; j4++) {
            float4 w4 = wrow[lane + 32 * j4];
            #pragma unroll
            for (int r = 0; r < 8; r++) {
                float4 v = xs[r][lane + 32 * j4];
                a[r] = fmaf(w4.x, v.x,
                       fmaf(w4.y, v.y,
                       fmaf(w4.z, v.z,
                       fmaf(w4.w, v.w, a[r]))));
            }
        }

        // merged fold: 9 shfls; lane 4*g ends holding batch g's total
        #pragma unroll
        for (int r = 0; r < 4; r++) {
            float send = (lane & 16) ? a[r] : a[r + 4];
            float recv = __shfl_xor_sync(0xffffffffu, send, 16);
            a[r] = ((lane & 16) ? a[r + 4] : a[r]) + recv;
        }
        #pragma unroll
        for (int r = 0; r < 2; r++) {
            float send = (lane & 8) ? a[r] : a[r + 2];
            float recv = __shfl_xor_sync(0xffffffffu, send, 8);
            a[r] = ((lane & 8) ? a[r + 2] : a[r]) + recv;
        }
        {
            float send = (lane & 4) ? a[0] : a[1];
            float recv = __shfl_xor_sync(0xffffffffu, send, 4);
            a[0] = ((lane & 4) ? a[1] : a[0]) + recv;
        }
        a[0] += __shfl_xor_sync(0xffffffffu, a[0], 2);
        a[0] += __shfl_xor_sync(0xffffffffu, a[0], 1);

        if ((lane & 3) == 0) {
            int r = lane >> 2;               // batch index within block
            int b = b0 + r;
            float p = __expf(a[0] + s_bias[o]);
            if (o >= 2 * KDIM) {
                int k = o - 2 * KDIM;
                p += kappa_old[(size_t)b * KDIM + k];
                out_kappa[(size_t)b * KDIM + k] = p;
            }
            s_par[r][o] = p;
        }
    }
    __syncthreads();

    // ---- stage 2: sparse phi, 240 (batch, gaussian) tasks over 8 warps ----
    for (int t = wid; t < 8 * KDIM; t += 8) {
        const int r = t / KDIM;
        const int k = t - r * KDIM;
        const float alpha = s_par[r][k];
        const float beta  = s_par[r][KDIM + k];
        const float kap   = s_par[r][2 * KDIM + k];
        const float rad = fminf(sqrtf(92.0f / beta), 1100.0f);
        const int lo = max(0, (int)(kap - rad));
        const int hi = min(LPAD, (int)(kap + rad) + 1);
        for (int l = lo + lane; l <= hi; l += 32) {
            float d = kap - (float)l;
            atomicAdd(&s_phi[r][l], alpha * __expf(-beta * d * d));
        }
    }
    __syncthreads();

    // ---- scale + store phi ----
    for (int i = tid; i < 8 * (LPAD + 1); i += 256) {
        int r = i / (LPAD + 1);
        int l = i - r * (LPAD + 1);
        out_phi[(size_t)(b0 + r) * (LPAD + 1) + l] = s_phi[r][l] * s_scale[r];
    }
}

// ---------------------------------------------------------------------------
// Kernel C: streaming w reduction — EXACT measured-best config (grid 2048,
// block 256, ~118us @ 73% DRAM ~= LTS cap for this pattern).  FROZEN.
// ---------------------------------------------------------------------------
__global__ __launch_bounds__(256) void wsum_kernel(
    const float4* __restrict__ onehots,   // [B, L*V/4]
    const float* __restrict__ phi,        // [B, L+1]
    float* __restrict__ out_w)            // [B, V]
{
    __shared__ float s_phi[LPAD];
    __shared__ float s_w[VDIM];

    const int bid = blockIdx.x;
    const int tid = threadIdx.x;

    #pragma unroll
    for (int i = tid; i < LPAD; i += 256)
        s_phi[i] = phi[(size_t)bid * (LPAD + 1) + i];
    if (tid < VDIM) s_w[tid] = 0.0f;
    __syncthreads();

    const float4* oh = onehots + (size_t)bid * (LPAD * VDIM / 4);

    float4 acc[5];
    int l0[5], cb[5];
    #pragma unroll
    for (int m = 0; m < 5; m++) {
        int e0 = 4 * tid + 1024 * m;
        l0[m] = e0 / VDIM;
        cb[m] = e0 % VDIM;
        acc[m] = make_float4(0.f, 0.f, 0.f, 0.f);
    }

    #pragma unroll 2
    for (int g = 0; g < 16; g++) {
        #pragma unroll
        for (int m = 0; m < 5; m++) {
            float4 v4 = __ldcs(&oh[tid + 256 * (m + 5 * g)]);
            float ph = s_phi[l0[m] + 64 * g];
            acc[m].x = fmaf(ph, v4.x, acc[m].x);
            acc[m].y = fmaf(ph, v4.y, acc[m].y);
            acc[m].z = fmaf(ph, v4.z, acc[m].z);
            acc[m].w = fmaf(ph, v4.w, acc[m].w);
        }
    }
    __syncthreads();

    #pragma unroll
    for (int m = 0; m < 5; m++) {
        atomicAdd(&s_w[cb[m] + 0], acc[m].x);
        atomicAdd(&s_w[cb[m] + 1], acc[m].y);
        atomicAdd(&s_w[cb[m] + 2], acc[m].z);
        atomicAdd(&s_w[cb[m] + 3], acc[m].w);
    }
    __syncthreads();

    if (tid < VDIM) out_w[(size_t)bid * VDIM + tid] = s_w[tid];
}

extern "C" void kernel_launch(void* const* d_in, const int* in_sizes, int n_in,
                              void* d_out, int out_size) {
    const float* x         = (const float*)d_in[0];
    const float* kappa_old = (const float*)d_in[1];
    const float4* onehots  = (const float4*)d_in[2];
    const float* text_lens = (const float*)d_in[3];
    const float* W         = (const float*)d_in[4];
    const float* bias      = (const float*)d_in[5];

    float* out = (float*)d_out;
    float* out_w     = out;                                  // [B, V]
    float* out_kappa = out + (size_t)BATCH * VDIM;           // [B, K]
    float* out_phi   = out + (size_t)BATCH * (VDIM + KDIM);  // [B, L+1]

    params_phi_kernel<<<BATCH / 8, 256>>>(x, kappa_old, text_lens, W, bias,
                                          out_kappa, out_phi);
    wsum_kernel<<<BATCH, 256>>>(onehots, out_phi, out_w);
}

// round 17
// speedup vs baseline: 1.0141x; 1.0141x over previous
#include <cuda_runtime.h>

#define BATCH 2048
#define CELL 512
#define KDIM 30
#define LPAD 1024
#define VDIM 80

// scratch: [B, 90] = alpha | beta | kappa (kappa pre-summed with kappa_old)
__device__ float g_params[BATCH * 3 * KDIM];

// ---------------------------------------------------------------------------
// Kernel A: params = exp(x @ W.T + b).  Measured-best (r14, 25.0us):
// 8 batches/block, 8 warps, launch_bounds(256,2) -> 128-reg budget, no
// spills, 2 blocks/SM, grid 256 = ONE wave.  8 batch accumulators share every
// coalesced W float4 load; 9-shfl merged fold; smem bias.
// Falsified alternatives: 4x8 reg tile (r13 spilled at 64-reg trap, r15 slower
// even with full regs: fewer rounds -> less cross-round ILP), reg caps (r5/r8),
// thread-per-output gather (r6), 16-batch blocks (r5), phi fusion (r16).
// ---------------------------------------------------------------------------
__global__ __launch_bounds__(256, 2) void params_kernel(
    const float* __restrict__ x,          // [B, CELL]
    const float* __restrict__ kappa_old,  // [B, K]
    const float* __restrict__ W,          // [3K, CELL]
    const float* __restrict__ bias,       // [3K]
    float* __restrict__ out_kappa)        // [B, K]
{
    __shared__ float4 xs[8][CELL / 4 + 1];   // 16.5 KB, rows bank-shifted
    __shared__ float s_bias[3 * KDIM];

    const int tid = threadIdx.x;
    const int wid = tid >> 5;                // 8 warps
    const int lane = tid & 31;
    const int b0 = blockIdx.x * 8;

    const float4* xg = (const float4*)(x + (size_t)b0 * CELL);
    for (int i = tid; i < 8 * CELL / 4; i += 256) {
        int r = i >> 7;
        int j = i & 127;
        xs[r][j] = xg[r * 128 + j];
    }
    if (tid < 3 * KDIM) s_bias[tid] = bias[tid];
    __syncthreads();

    // 90 outputs round-robin over 8 warps (11-12 each), 8 batch accs
    for (int o = wid; o < 3 * KDIM; o += 8) {
        const float4* wrow = (const float4*)(W + (size_t)o * CELL);
        float a[8];
        #pragma unroll
        for (int r = 0; r < 8; r++) a[r] = 0.0f;

        #pragma unroll
        for (int j4 = 0; j4 < 4; j4++) {
            float4 w4 = wrow[lane + 32 * j4];
            #pragma unroll
            for (int r = 0; r < 8; r++) {
                float4 v = xs[r][lane + 32 * j4];
                a[r] = fmaf(w4.x, v.x,
                       fmaf(w4.y, v.y,
                       fmaf(w4.z, v.z,
                       fmaf(w4.w, v.w, a[r]))));
            }
        }

        // merged fold: 9 shfls; lane 4*g ends holding batch g's total
        #pragma unroll
        for (int r = 0; r < 4; r++) {
            float send = (lane & 16) ? a[r] : a[r + 4];
            float recv = __shfl_xor_sync(0xffffffffu, send, 16);
            a[r] = ((lane & 16) ? a[r + 4] : a[r]) + recv;
        }
        #pragma unroll
        for (int r = 0; r < 2; r++) {
            float send = (lane & 8) ? a[r] : a[r + 2];
            float recv = __shfl_xor_sync(0xffffffffu, send, 8);
            a[r] = ((lane & 8) ? a[r + 2] : a[r]) + recv;
        }
        {
            float send = (lane & 4) ? a[0] : a[1];
            float recv = __shfl_xor_sync(0xffffffffu, send, 4);
            a[0] = ((lane & 4) ? a[1] : a[0]) + recv;
        }
        a[0] += __shfl_xor_sync(0xffffffffu, a[0], 2);
        a[0] += __shfl_xor_sync(0xffffffffu, a[0], 1);

        if ((lane & 3) == 0) {
            int r = lane >> 2;               // batch index within block
            int b = b0 + r;
            float p = __expf(a[0] + s_bias[o]);
            if (o >= 2 * KDIM) {
                int k = o - 2 * KDIM;
                p += kappa_old[(size_t)b * KDIM + k];
                out_kappa[(size_t)b * KDIM + k] = p;
            }
            g_params[(size_t)b * (3 * KDIM) + o] = p;
        }
    }
}

// ---------------------------------------------------------------------------
// Kernel B: sparse phi.  One block per batch (2048 blocks spread the 30
// Gaussians/batch to ~4 task-rounds/warp; fusing into params multiplies this
// x8 — measured worse, r16).  Gaussian k only touched where
// beta*(kappa-l)^2 < 92 (expf underflows to 0, matching fp32 reference).
// ---------------------------------------------------------------------------
__global__ __launch_bounds__(256) void phi_kernel(
    const float* __restrict__ text_lens,  // [B, 1]
    float* __restrict__ out_phi)          // [B, L+1]
{
    __shared__ float s_par[3 * KDIM];
    __shared__ float s_phi[LPAD + 1];

    const int bid = blockIdx.x;
    const int tid = threadIdx.x;
    const int wid = tid >> 5;
    const int lane = tid & 31;

    if (tid < 3 * KDIM)
        s_par[tid] = g_params[(size_t)bid * (3 * KDIM) + tid];
    #pragma unroll
    for (int l = tid; l <= LPAD; l += 256)
        s_phi[l] = 0.0f;
    __syncthreads();

    for (int k = wid; k < KDIM; k += 8) {
        const float alpha = s_par[k];
        const float beta  = s_par[KDIM + k];
        const float kap   = s_par[2 * KDIM + k];
        const float r = fminf(sqrtf(92.0f / beta), 1100.0f);
        const int lo = max(0, (int)(kap - r));
        const int hi = min(LPAD, (int)(kap + r) + 1);
        for (int l = lo + lane; l <= hi; l += 32) {
            float d = kap - (float)l;
            atomicAdd(&s_phi[l], alpha * __expf(-beta * d * d));
        }
    }
    __syncthreads();

    const float scale = (float)LPAD / text_lens[bid];
    for (int l = tid; l <= LPAD; l += 256)
        out_phi[(size_t)bid * (LPAD + 1) + l] = s_phi[l] * scale;
}

// ---------------------------------------------------------------------------
// Kernel C: streaming w reduction — measured-best config (grid 2048, block
// 256, ~118us @ 73% DRAM = LTS-cap ceiling for this pattern; invariant across
// persistence/L-split/min-blocks/chunking variants).  FROZEN.
// ---------------------------------------------------------------------------
__global__ __launch_bounds__(256) void wsum_kernel(
    const float4* __restrict__ onehots,   // [B, L*V/4]
    const float* __restrict__ phi,        // [B, L+1]
    float* __restrict__ out_w)            // [B, V]
{
    __shared__ float s_phi[LPAD];
    __shared__ float s_w[VDIM];

    const int bid = blockIdx.x;
    const int tid = threadIdx.x;

    #pragma unroll
    for (int i = tid; i < LPAD; i += 256)
        s_phi[i] = phi[(size_t)bid * (LPAD + 1) + i];
    if (tid < VDIM) s_w[tid] = 0.0f;
    __syncthreads();

    const float4* oh = onehots + (size_t)bid * (LPAD * VDIM / 4);

    float4 acc[5];
    int l0[5], cb[5];
    #pragma unroll
    for (int m = 0; m < 5; m++) {
        int e0 = 4 * tid + 1024 * m;
        l0[m] = e0 / VDIM;
        cb[m] = e0 % VDIM;
        acc[m] = make_float4(0.f, 0.f, 0.f, 0.f);
    }

    #pragma unroll 2
    for (int g = 0; g < 16; g++) {
        #pragma unroll
        for (int m = 0; m < 5; m++) {
            float4 v4 = __ldcs(&oh[tid + 256 * (m + 5 * g)]);
            float ph = s_phi[l0[m] + 64 * g];
            acc[m].x = fmaf(ph, v4.x, acc[m].x);
            acc[m].y = fmaf(ph, v4.y, acc[m].y);
            acc[m].z = fmaf(ph, v4.z, acc[m].z);
            acc[m].w = fmaf(ph, v4.w, acc[m].w);
        }
    }
    __syncthreads();

    #pragma unroll
    for (int m = 0; m < 5; m++) {
        atomicAdd(&s_w[cb[m] + 0], acc[m].x);
        atomicAdd(&s_w[cb[m] + 1], acc[m].y);
        atomicAdd(&s_w[cb[m] + 2], acc[m].z);
        atomicAdd(&s_w[cb[m] + 3], acc[m].w);
    }
    __syncthreads();

    if (tid < VDIM) out_w[(size_t)bid * VDIM + tid] = s_w[tid];
}

extern "C" void kernel_launch(void* const* d_in, const int* in_sizes, int n_in,
                              void* d_out, int out_size) {
    const float* x         = (const float*)d_in[0];
    const float* kappa_old = (const float*)d_in[1];
    const float4* onehots  = (const float4*)d_in[2];
    const float* text_lens = (const float*)d_in[3];
    const float* W         = (const float*)d_in[4];
    const float* bias      = (const float*)d_in[5];

    float* out = (float*)d_out;
    float* out_w     = out;                                  // [B, V]
    float* out_kappa = out + (size_t)BATCH * VDIM;           // [B, K]
    float* out_phi   = out + (size_t)BATCH * (VDIM + KDIM);  // [B, L+1]

    params_kernel<<<BATCH / 8, 256>>>(x, kappa_old, W, bias, out_kappa);
    phi_kernel<<<BATCH, 256>>>(text_lens, out_phi);
    wsum_kernel<<<BATCH, 256>>>(onehots, out_phi, out_w);
}